// round 1
// baseline (speedup 1.0000x reference)
#include <cuda_runtime.h>

#define BB 8
#define NN 1024
#define HH 512
#define NHEAD 8
#define HD 64

// Scratch (allocation-free rule: __device__ globals)
__device__ float g_act[(size_t)BB * NN * 4 * HH];   // 8192 x 2048 : [U | Q | K | V]
__device__ float g_attn[(size_t)BB * NN * HH];      // 8192 x 512
__device__ float g_ts[BB * NN];                     // timestamps as fp32 (seconds)

// ---------------------------------------------------------------------------
// Timestamp normalization. Reference does astype(float32) then /1e9.
// Dataset dtype may be int32 (jax x64 off) or int64; values < 2^31 so under
// int64 layout all high words are 0. Detect deterministically from data.
// ---------------------------------------------------------------------------
__global__ void ts_convert_kernel(const int* __restrict__ t, float* __restrict__ out) {
    bool is64 = (t[1] == 0 && t[3] == 0 && t[5] == 0 && t[7] == 0);
    int i = blockIdx.x * blockDim.x + threadIdx.x;
    if (i < BB * NN) {
        long long v = is64 ? ((const long long*)t)[i] : (long long)t[i];
        float tv = (float)v;          // match astype(float32)
        out[i] = tv / 1e9f;           // match fp32 division
    }
}

// ---------------------------------------------------------------------------
// Tiled SGEMM: C[m,n] = sum_k A[m,k] * W[n,k] + bias[n]
//   SILU: apply x*sigmoid(x) epilogue (GEMM1)
//   GATE: A-element multiplied by A2[m,k] on load (GEMM2 gating by U)
// BM=BN=128, BK=8, 256 threads, 8x8 micro-tile.
// ---------------------------------------------------------------------------
template<bool SILU, bool GATE>
__global__ __launch_bounds__(256) void sgemm_kernel(
    const float* __restrict__ A, int lda,
    const float* __restrict__ A2, int lda2,
    const float* __restrict__ W,
    const float* __restrict__ bias,
    float* __restrict__ C, int ldc, int K)
{
    __shared__ float As[8][128];
    __shared__ float Bs[8][128];

    int tid = threadIdx.x;
    int tx = tid & 15;          // n micro-tile
    int ty = tid >> 4;          // m micro-tile
    int m0 = blockIdx.y * 128;
    int n0 = blockIdx.x * 128;

    int arow = tid >> 1;        // 0..127
    int acol = (tid & 1) * 4;   // 0 or 4

    float acc[8][8];
    #pragma unroll
    for (int i = 0; i < 8; i++)
        #pragma unroll
        for (int j = 0; j < 8; j++) acc[i][j] = 0.f;

    for (int k0 = 0; k0 < K; k0 += 8) {
        float4 av = *(const float4*)(A + (size_t)(m0 + arow) * lda + k0 + acol);
        if (GATE) {
            float4 uv = *(const float4*)(A2 + (size_t)(m0 + arow) * lda2 + k0 + acol);
            av.x *= uv.x; av.y *= uv.y; av.z *= uv.z; av.w *= uv.w;
        }
        float4 bv = *(const float4*)(W + (size_t)(n0 + arow) * K + k0 + acol);

        __syncthreads();
        As[acol + 0][arow] = av.x; As[acol + 1][arow] = av.y;
        As[acol + 2][arow] = av.z; As[acol + 3][arow] = av.w;
        Bs[acol + 0][arow] = bv.x; Bs[acol + 1][arow] = bv.y;
        Bs[acol + 2][arow] = bv.z; Bs[acol + 3][arow] = bv.w;
        __syncthreads();

        #pragma unroll
        for (int kk = 0; kk < 8; kk++) {
            float a[8], b[8];
            *(float4*)&a[0] = *(const float4*)&As[kk][ty * 8];
            *(float4*)&a[4] = *(const float4*)&As[kk][ty * 8 + 4];
            *(float4*)&b[0] = *(const float4*)&Bs[kk][tx * 8];
            *(float4*)&b[4] = *(const float4*)&Bs[kk][tx * 8 + 4];
            #pragma unroll
            for (int i = 0; i < 8; i++)
                #pragma unroll
                for (int j = 0; j < 8; j++)
                    acc[i][j] += a[i] * b[j];
        }
    }

    #pragma unroll
    for (int i = 0; i < 8; i++) {
        int m = m0 + ty * 8 + i;
        #pragma unroll
        for (int j = 0; j < 8; j++) {
            int n = n0 + tx * 8 + j;
            float v = acc[i][j] + bias[n];
            if (SILU) v = v / (1.f + expf(-v));
            C[(size_t)m * ldc + n] = v;
        }
    }
}

// ---------------------------------------------------------------------------
// Fused attention: per (b,h,q-tile of 64). Causal k-tiles of 32.
//   scores = QK^T * 0.125 + pos_w[n-1+k-q] + ts_w[bucket(|tsq-tsk|)]
//   w = silu(scores) masked to k<=q;  acc += w @ V
// Q/K/V read from g_act segments. K stored transposed [d][k] in smem so the
// score inner loop does conflict-free float4 reads along k.
// ---------------------------------------------------------------------------
__global__ __launch_bounds__(256) void attn_kernel(
    const float* __restrict__ act,
    const float* __restrict__ ts,
    const float* __restrict__ ts_w,
    const float* __restrict__ pos_w,
    float* __restrict__ attn_out)
{
    __shared__ float Qs[64][68];
    __shared__ float Kt[64][36];   // transposed: [d][k]
    __shared__ float Vs[32][68];
    __shared__ float Ss[64][33];
    __shared__ float tsq[64];
    __shared__ float tsk[32];

    int tid = threadIdx.x;
    int qt = blockIdx.x;
    int bh = blockIdx.y;
    int b = bh >> 3, h = bh & 7;
    int q0 = qt * 64;

    const float* actb = act + (size_t)b * NN * 2048;

    // load Q tile [64 x 64]
    for (int i = tid; i < 64 * 16; i += 256) {
        int r = i >> 4, c4 = (i & 15) * 4;
        *(float4*)&Qs[r][c4] =
            *(const float4*)(actb + (size_t)(q0 + r) * 2048 + 512 + h * 64 + c4);
    }
    if (tid < 64) {
        int qq = min(q0 + tid + 1, NN - 1);   // ext[i+1] = ts[min(i+1, n-1)]
        tsq[tid] = ts[b * NN + qq];
    }

    int ty2 = tid >> 4, tx2 = tid & 15;  // stage2: q = ty2*4+i, d = tx2*4+..
    int ty1 = tid >> 3, tx1 = tid & 7;   // stage1: q = ty1*2+i, k = tx1*4+j
    int qa = ty1 * 2, ka = tx1 * 4;

    float acc[4][4] = {};

    int ktmax = (q0 + 63) >> 5;
    for (int kt = 0; kt <= ktmax; kt++) {
        int k0 = kt << 5;
        __syncthreads();  // protect Kt/Vs/tsk from previous iteration's readers

        // load K (transpose into Kt) and V tiles [32 x 64]
        for (int i = tid; i < 32 * 16; i += 256) {
            int r = i >> 4, c4 = (i & 15) * 4;
            float4 kv = *(const float4*)(actb + (size_t)(k0 + r) * 2048 + 1024 + h * 64 + c4);
            Kt[c4 + 0][r] = kv.x; Kt[c4 + 1][r] = kv.y;
            Kt[c4 + 2][r] = kv.z; Kt[c4 + 3][r] = kv.w;
            *(float4*)&Vs[r][c4] =
                *(const float4*)(actb + (size_t)(k0 + r) * 2048 + 1536 + h * 64 + c4);
        }
        if (tid < 32) tsk[tid] = ts[b * NN + k0 + tid];
        __syncthreads();

        // stage 1: scores (2 q x 4 k per thread)
        float s[2][4] = {};
        #pragma unroll
        for (int d = 0; d < 64; d += 4) {
            float4 qv0 = *(const float4*)&Qs[qa][d];
            float4 qv1 = *(const float4*)&Qs[qa + 1][d];
            float4 k0v = *(const float4*)&Kt[d + 0][ka];
            float4 k1v = *(const float4*)&Kt[d + 1][ka];
            float4 k2v = *(const float4*)&Kt[d + 2][ka];
            float4 k3v = *(const float4*)&Kt[d + 3][ka];
            s[0][0] += qv0.x * k0v.x + qv0.y * k1v.x + qv0.z * k2v.x + qv0.w * k3v.x;
            s[0][1] += qv0.x * k0v.y + qv0.y * k1v.y + qv0.z * k2v.y + qv0.w * k3v.y;
            s[0][2] += qv0.x * k0v.z + qv0.y * k1v.z + qv0.z * k2v.z + qv0.w * k3v.z;
            s[0][3] += qv0.x * k0v.w + qv0.y * k1v.w + qv0.z * k2v.w + qv0.w * k3v.w;
            s[1][0] += qv1.x * k0v.x + qv1.y * k1v.x + qv1.z * k2v.x + qv1.w * k3v.x;
            s[1][1] += qv1.x * k0v.y + qv1.y * k1v.y + qv1.z * k2v.y + qv1.w * k3v.y;
            s[1][2] += qv1.x * k0v.z + qv1.y * k1v.z + qv1.z * k2v.z + qv1.w * k3v.z;
            s[1][3] += qv1.x * k0v.w + qv1.y * k1v.w + qv1.z * k2v.w + qv1.w * k3v.w;
        }

        // bias + silu + causal mask -> Ss
        #pragma unroll
        for (int i = 0; i < 2; i++) {
            int q = q0 + qa + i;
            float tq = tsq[qa + i];
            #pragma unroll
            for (int j = 0; j < 4; j++) {
                int k = k0 + ka + j;
                float val = 0.f;
                if (k <= q) {
                    float sc = s[i][j] * 0.125f;
                    float ad = fmaxf(fabsf(tq - tsk[ka + j]), 1.0f);
                    int bucket = (int)floorf(logf(ad) / 0.301f);
                    bucket = bucket < 0 ? 0 : (bucket > 64 ? 64 : bucket);
                    sc += pos_w[NN - 1 + k - q] + ts_w[bucket];
                    val = sc / (1.f + expf(-sc));
                }
                Ss[qa + i][ka + j] = val;
            }
        }
        __syncthreads();

        // stage 2: acc += Ss @ V (4 q x 4 d per thread)
        #pragma unroll
        for (int k = 0; k < 32; k++) {
            float4 vv = *(const float4*)&Vs[k][tx2 * 4];
            #pragma unroll
            for (int i = 0; i < 4; i++) {
                float w = Ss[ty2 * 4 + i][k];
                acc[i][0] += w * vv.x;
                acc[i][1] += w * vv.y;
                acc[i][2] += w * vv.z;
                acc[i][3] += w * vv.w;
            }
        }
    }

    #pragma unroll
    for (int i = 0; i < 4; i++) {
        int q = q0 + ty2 * 4 + i;
        float4 o = make_float4(acc[i][0], acc[i][1], acc[i][2], acc[i][3]);
        *(float4*)(attn_out + ((size_t)b * NN + q) * HH + h * 64 + tx2 * 4) = o;
    }
}

// ---------------------------------------------------------------------------
extern "C" void kernel_launch(void* const* d_in, const int* in_sizes, int n_in,
                              void* d_out, int out_size) {
    const float* x     = (const float*)d_in[0];
    const int*   tsi   = (const int*)  d_in[1];
    // d_in[2] = attn_mask (tril causal, handled analytically)
    const float* f1_w  = (const float*)d_in[3];
    const float* f1_b  = (const float*)d_in[4];
    const float* f2_w  = (const float*)d_in[5];
    const float* f2_b  = (const float*)d_in[6];
    const float* ts_w  = (const float*)d_in[7];
    const float* pos_w = (const float*)d_in[8];
    float* out = (float*)d_out;

    float *actp, *attnp, *tsp;
    cudaGetSymbolAddress((void**)&actp, g_act);
    cudaGetSymbolAddress((void**)&attnp, g_attn);
    cudaGetSymbolAddress((void**)&tsp, g_ts);

    ts_convert_kernel<<<32, 256>>>(tsi, tsp);

    // GEMM1 + SiLU: [8192,512] @ [2048,512]^T -> g_act [8192,2048]
    sgemm_kernel<true, false><<<dim3(16, 64), 256>>>(
        x, HH, nullptr, 0, f1_w, f1_b, actp, 4 * HH, HH);

    // Attention: per (q-tile, b*head)
    attn_kernel<<<dim3(16, 64), 256>>>(actp, tsp, ts_w, pos_w, attnp);

    // GEMM2 with fused U gating: (attn * U) @ [512,512]^T + f2_b -> out
    sgemm_kernel<false, true><<<dim3(4, 64), 256>>>(
        attnp, HH, actp, 4 * HH, f2_w, f2_b, out, HH, HH);
}

// round 3
// speedup vs baseline: 1.7648x; 1.7648x over previous
#include <cuda_runtime.h>
#include <cstdint>

#define BB 8
#define NN 1024
#define HH 512

// Scratch (allocation-free rule: __device__ globals)
__device__ float g_act[(size_t)BB * NN * 4 * HH];   // 8192 x 2048 : [U | Q | K | V]
__device__ float g_attn[(size_t)BB * NN * HH];      // 8192 x 512 (gated, tf32-rounded)
__device__ float g_ts[BB * NN];                     // timestamps fp32 (seconds)
__device__ float g_xr[(size_t)BB * NN * HH];        // x rounded to tf32
__device__ float g_w1r[(size_t)4 * HH * HH];        // f1_w rounded to tf32
__device__ float g_w2r[(size_t)HH * HH];            // f2_w rounded to tf32

// ---------------------------------------------------------------------------
__device__ __forceinline__ uint32_t smem_u32(const void* p) {
    uint32_t a;
    asm("{ .reg .u64 t; cvta.to.shared.u64 t, %1; cvt.u32.u64 %0, t; }" : "=r"(a) : "l"(p));
    return a;
}
__device__ __forceinline__ float to_tf32(float x) {
    float r; asm("cvt.rna.tf32.f32 %0, %1;" : "=f"(r) : "f"(x)); return r;
}

#define CP_ASYNC16(dst, src) \
    asm volatile("cp.async.cg.shared.global [%0], [%1], 16;" :: "r"(dst), "l"(src) : "memory")
#define CP_COMMIT() asm volatile("cp.async.commit_group;" ::: "memory")
#define CP_WAIT1()  asm volatile("cp.async.wait_group 1;" ::: "memory")
#define CP_WAIT0()  asm volatile("cp.async.wait_group 0;" ::: "memory")

#define MMA_TF32(c, a, b)                                                        \
    asm volatile("mma.sync.aligned.m16n8k8.row.col.f32.tf32.tf32.f32 "           \
        "{%0,%1,%2,%3}, {%4,%5,%6,%7}, {%8,%9}, {%0,%1,%2,%3};"                  \
        : "+f"((c)[0]), "+f"((c)[1]), "+f"((c)[2]), "+f"((c)[3])                  \
        : "r"((a)[0]), "r"((a)[1]), "r"((a)[2]), "r"((a)[3]),                     \
          "r"((b)[0]), "r"((b)[1]))

// ---------------------------------------------------------------------------
// Small prep kernels
// ---------------------------------------------------------------------------
__global__ void ts_convert_kernel(const int* __restrict__ t, float* __restrict__ out) {
    bool is64 = (t[1] == 0 && t[3] == 0 && t[5] == 0 && t[7] == 0);
    int i = blockIdx.x * blockDim.x + threadIdx.x;
    if (i < BB * NN) {
        long long v = is64 ? ((const long long*)t)[i] : (long long)t[i];
        float tv = (float)v;
        out[i] = tv / 1e9f;
    }
}

__global__ void round_tf32_kernel(const float* __restrict__ in, float* __restrict__ out, int n) {
    int i = blockIdx.x * blockDim.x + threadIdx.x;
    if (i < n) out[i] = to_tf32(in[i]);
}

// ---------------------------------------------------------------------------
// mma.sync tf32 GEMM: C[m,n] = sum_k A[m,k]*W[n,k] + bias[n]  (optional SiLU)
// CTA tile 128x256, warp tile 64x64 (warps 2x4), K-chunk 32, double-buffered
// cp.async. A, W pre-rounded to tf32 (rna). K fixed at 512.
// Smem: rows padded to 36 floats -> conflict-free fragment LDS, 16B-aligned
// cp.async (144B row stride).
// ---------------------------------------------------------------------------
#define GK 512
#define LDS_K 36
#define A_BYTES (128 * LDS_K * 4)          // 18432
#define B_BYTES (256 * LDS_K * 4)          // 36864
#define STAGE_BYTES (A_BYTES + B_BYTES)    // 55296
#define GEMM_SMEM (2 * STAGE_BYTES)        // 110592

template<bool SILU>
__global__ __launch_bounds__(256, 1) void gemm_mma_kernel(
    const float* __restrict__ A, const float* __restrict__ W,
    const float* __restrict__ bias, float* __restrict__ C, int ldc)
{
    extern __shared__ char smem[];
    const uint32_t sb = smem_u32(smem);
    const int tid = threadIdx.x;
    const int lane = tid & 31;
    const int wid = tid >> 5;
    const int wm = wid >> 2;            // 0..1
    const int wn = wid & 3;             // 0..3
    const int l4 = lane >> 2;           // 0..7
    const int lc = lane & 3;            // 0..3
    const int m0 = blockIdx.y * 128;
    const int n0 = blockIdx.x * 256;

    // stage loader: A rows [m0,m0+128) x 32 floats, B rows [n0,n0+256) x 32
    auto load_stage = [&](int s, int buf) {
        uint32_t base = sb + buf * STAGE_BYTES;
        const float* a0 = A + (size_t)m0 * GK + s * 32;
        #pragma unroll
        for (int q = 0; q < 4; q++) {          // 128 rows * 8 segs / 256 thr
            int idx = q * 256 + tid;
            int r = idx >> 3, c = idx & 7;
            CP_ASYNC16(base + r * (LDS_K * 4) + c * 16, a0 + (size_t)r * GK + c * 4);
        }
        const float* b0 = W + (size_t)n0 * GK + s * 32;
        #pragma unroll
        for (int q = 0; q < 8; q++) {          // 256 rows * 8 segs / 256 thr
            int idx = q * 256 + tid;
            int r = idx >> 3, c = idx & 7;
            CP_ASYNC16(base + A_BYTES + r * (LDS_K * 4) + c * 16, b0 + (size_t)r * GK + c * 4);
        }
    };

    load_stage(0, 0); CP_COMMIT();
    load_stage(1, 1); CP_COMMIT();

    float acc[4][8][4];
    #pragma unroll
    for (int mt = 0; mt < 4; mt++)
        #pragma unroll
        for (int nt = 0; nt < 8; nt++)
            #pragma unroll
            for (int i = 0; i < 4; i++) acc[mt][nt][i] = 0.f;

    const int NSTAGE = GK / 32;   // 16
    #pragma unroll 1
    for (int s = 0; s < NSTAGE; s++) {
        if (s == NSTAGE - 1) { CP_WAIT0(); } else { CP_WAIT1(); }
        __syncthreads();

        const float* As = (const float*)(smem + (s & 1) * STAGE_BYTES);
        const float* Bs = (const float*)(smem + (s & 1) * STAGE_BYTES + A_BYTES);
        const int arow = wm * 64 + l4;
        const int brow = wn * 64 + l4;

        #pragma unroll
        for (int kk = 0; kk < 4; kk++) {
            int kA = kk * 8 + lc;
            uint32_t a[4][4], b[8][2];
            #pragma unroll
            for (int mt = 0; mt < 4; mt++) {
                const float* p = As + (arow + mt * 16) * LDS_K + kA;
                a[mt][0] = __float_as_uint(p[0]);
                a[mt][1] = __float_as_uint(p[8 * LDS_K]);
                a[mt][2] = __float_as_uint(p[4]);
                a[mt][3] = __float_as_uint(p[8 * LDS_K + 4]);
            }
            #pragma unroll
            for (int nt = 0; nt < 8; nt++) {
                const float* p = Bs + (brow + nt * 8) * LDS_K + kA;
                b[nt][0] = __float_as_uint(p[0]);
                b[nt][1] = __float_as_uint(p[4]);
            }
            #pragma unroll
            for (int mt = 0; mt < 4; mt++)
                #pragma unroll
                for (int nt = 0; nt < 8; nt++)
                    MMA_TF32(acc[mt][nt], a[mt], b[nt]);
        }

        __syncthreads();
        if (s + 2 < NSTAGE) { load_stage(s + 2, s & 1); CP_COMMIT(); }
    }

    // Epilogue: bias (+ SiLU), direct float2 stores
    #pragma unroll
    for (int mt = 0; mt < 4; mt++) {
        int r0 = m0 + wm * 64 + mt * 16 + l4;
        #pragma unroll
        for (int nt = 0; nt < 8; nt++) {
            int c0 = n0 + wn * 64 + nt * 8 + 2 * lc;
            float bv0 = bias[c0], bv1 = bias[c0 + 1];
            float v0 = acc[mt][nt][0] + bv0;
            float v1 = acc[mt][nt][1] + bv1;
            float v2 = acc[mt][nt][2] + bv0;
            float v3 = acc[mt][nt][3] + bv1;
            if (SILU) {
                v0 = __fdividef(v0, 1.f + __expf(-v0));
                v1 = __fdividef(v1, 1.f + __expf(-v1));
                v2 = __fdividef(v2, 1.f + __expf(-v2));
                v3 = __fdividef(v3, 1.f + __expf(-v3));
            }
            *(float2*)(C + (size_t)r0 * ldc + c0) = make_float2(v0, v1);
            *(float2*)(C + (size_t)(r0 + 8) * ldc + c0) = make_float2(v2, v3);
        }
    }
}

// ---------------------------------------------------------------------------
// Fused attention (SIMT fp32) with fused U-gating + tf32 rounding on store
// ---------------------------------------------------------------------------
__global__ __launch_bounds__(256) void attn_kernel(
    const float* __restrict__ act,
    const float* __restrict__ ts,
    const float* __restrict__ ts_w,
    const float* __restrict__ pos_w,
    float* __restrict__ attn_out)
{
    __shared__ float Qs[64][68];
    __shared__ float Kt[64][36];
    __shared__ float Vs[32][68];
    __shared__ float Ss[64][33];
    __shared__ float tsq[64];
    __shared__ float tsk[32];

    int tid = threadIdx.x;
    int qt = blockIdx.x;
    int bh = blockIdx.y;
    int b = bh >> 3, h = bh & 7;
    int q0 = qt * 64;

    const float* actb = act + (size_t)b * NN * 2048;

    for (int i = tid; i < 64 * 16; i += 256) {
        int r = i >> 4, c4 = (i & 15) * 4;
        *(float4*)&Qs[r][c4] =
            *(const float4*)(actb + (size_t)(q0 + r) * 2048 + 512 + h * 64 + c4);
    }
    if (tid < 64) {
        int qq = min(q0 + tid + 1, NN - 1);
        tsq[tid] = ts[b * NN + qq];
    }

    int ty2 = tid >> 4, tx2 = tid & 15;
    int ty1 = tid >> 3, tx1 = tid & 7;
    int qa = ty1 * 2, ka = tx1 * 4;

    float acc[4][4] = {};

    int ktmax = (q0 + 63) >> 5;
    for (int kt = 0; kt <= ktmax; kt++) {
        int k0 = kt << 5;
        __syncthreads();

        for (int i = tid; i < 32 * 16; i += 256) {
            int r = i >> 4, c4 = (i & 15) * 4;
            float4 kv = *(const float4*)(actb + (size_t)(k0 + r) * 2048 + 1024 + h * 64 + c4);
            Kt[c4 + 0][r] = kv.x; Kt[c4 + 1][r] = kv.y;
            Kt[c4 + 2][r] = kv.z; Kt[c4 + 3][r] = kv.w;
            *(float4*)&Vs[r][c4] =
                *(const float4*)(actb + (size_t)(k0 + r) * 2048 + 1536 + h * 64 + c4);
        }
        if (tid < 32) tsk[tid] = ts[b * NN + k0 + tid];
        __syncthreads();

        float s[2][4] = {};
        #pragma unroll
        for (int d = 0; d < 64; d += 4) {
            float4 qv0 = *(const float4*)&Qs[qa][d];
            float4 qv1 = *(const float4*)&Qs[qa + 1][d];
            float4 k0v = *(const float4*)&Kt[d + 0][ka];
            float4 k1v = *(const float4*)&Kt[d + 1][ka];
            float4 k2v = *(const float4*)&Kt[d + 2][ka];
            float4 k3v = *(const float4*)&Kt[d + 3][ka];
            s[0][0] += qv0.x * k0v.x + qv0.y * k1v.x + qv0.z * k2v.x + qv0.w * k3v.x;
            s[0][1] += qv0.x * k0v.y + qv0.y * k1v.y + qv0.z * k2v.y + qv0.w * k3v.y;
            s[0][2] += qv0.x * k0v.z + qv0.y * k1v.z + qv0.z * k2v.z + qv0.w * k3v.z;
            s[0][3] += qv0.x * k0v.w + qv0.y * k1v.w + qv0.z * k2v.w + qv0.w * k3v.w;
            s[1][0] += qv1.x * k0v.x + qv1.y * k1v.x + qv1.z * k2v.x + qv1.w * k3v.x;
            s[1][1] += qv1.x * k0v.y + qv1.y * k1v.y + qv1.z * k2v.y + qv1.w * k3v.y;
            s[1][2] += qv1.x * k0v.z + qv1.y * k1v.z + qv1.z * k2v.z + qv1.w * k3v.z;
            s[1][3] += qv1.x * k0v.w + qv1.y * k1v.w + qv1.z * k2v.w + qv1.w * k3v.w;
        }

        #pragma unroll
        for (int i = 0; i < 2; i++) {
            int q = q0 + qa + i;
            float tq = tsq[qa + i];
            #pragma unroll
            for (int j = 0; j < 4; j++) {
                int k = k0 + ka + j;
                float val = 0.f;
                if (k <= q) {
                    float sc = s[i][j] * 0.125f;
                    float ad = fmaxf(fabsf(tq - tsk[ka + j]), 1.0f);
                    int bucket = (int)floorf(__logf(ad) * 3.3222591f);
                    bucket = bucket < 0 ? 0 : (bucket > 64 ? 64 : bucket);
                    sc += pos_w[NN - 1 + k - q] + ts_w[bucket];
                    val = __fdividef(sc, 1.f + __expf(-sc));
                }
                Ss[qa + i][ka + j] = val;
            }
        }
        __syncthreads();

        #pragma unroll
        for (int k = 0; k < 32; k++) {
            float4 vv = *(const float4*)&Vs[k][tx2 * 4];
            #pragma unroll
            for (int i = 0; i < 4; i++) {
                float w = Ss[ty2 * 4 + i][k];
                acc[i][0] += w * vv.x;
                acc[i][1] += w * vv.y;
                acc[i][2] += w * vv.z;
                acc[i][3] += w * vv.w;
            }
        }
    }

    #pragma unroll
    for (int i = 0; i < 4; i++) {
        int q = q0 + ty2 * 4 + i;
        float4 uv = *(const float4*)(actb + (size_t)q * 2048 + h * 64 + tx2 * 4);
        float4 o;
        o.x = to_tf32(acc[i][0] * uv.x);
        o.y = to_tf32(acc[i][1] * uv.y);
        o.z = to_tf32(acc[i][2] * uv.z);
        o.w = to_tf32(acc[i][3] * uv.w);
        *(float4*)(attn_out + ((size_t)b * NN + q) * HH + h * 64 + tx2 * 4) = o;
    }
}

// ---------------------------------------------------------------------------
extern "C" void kernel_launch(void* const* d_in, const int* in_sizes, int n_in,
                              void* d_out, int out_size) {
    const float* x     = (const float*)d_in[0];
    const int*   tsi   = (const int*)  d_in[1];
    const float* f1_w  = (const float*)d_in[3];
    const float* f1_b  = (const float*)d_in[4];
    const float* f2_w  = (const float*)d_in[5];
    const float* f2_b  = (const float*)d_in[6];
    const float* ts_w  = (const float*)d_in[7];
    const float* pos_w = (const float*)d_in[8];
    float* out = (float*)d_out;

    float *actp, *attnp, *tsp, *xrp, *w1p, *w2p;
    cudaGetSymbolAddress((void**)&actp, g_act);
    cudaGetSymbolAddress((void**)&attnp, g_attn);
    cudaGetSymbolAddress((void**)&tsp, g_ts);
    cudaGetSymbolAddress((void**)&xrp, g_xr);
    cudaGetSymbolAddress((void**)&w1p, g_w1r);
    cudaGetSymbolAddress((void**)&w2p, g_w2r);

    cudaFuncSetAttribute(gemm_mma_kernel<true>,
                         cudaFuncAttributeMaxDynamicSharedMemorySize, GEMM_SMEM);
    cudaFuncSetAttribute(gemm_mma_kernel<false>,
                         cudaFuncAttributeMaxDynamicSharedMemorySize, GEMM_SMEM);

    ts_convert_kernel<<<32, 256>>>(tsi, tsp);

    // Round MMA inputs to tf32 (RNA) for unbiased tensor-core accumulation
    round_tf32_kernel<<<(BB * NN * HH + 255) / 256, 256>>>(x, xrp, BB * NN * HH);
    round_tf32_kernel<<<(4 * HH * HH + 255) / 256, 256>>>(f1_w, w1p, 4 * HH * HH);
    round_tf32_kernel<<<(HH * HH + 255) / 256, 256>>>(f2_w, w2p, HH * HH);

    // GEMM1 + SiLU: [8192,512] @ [2048,512]^T -> g_act [8192,2048]
    gemm_mma_kernel<true><<<dim3(8, 64), 256, GEMM_SMEM>>>(xrp, w1p, f1_b, actp, 4 * HH);

    // Attention (+ fused U gating, tf32 round): -> g_attn
    attn_kernel<<<dim3(16, 64), 256>>>(actp, tsp, ts_w, pos_w, attnp);

    // GEMM2: gated @ [512,512]^T + f2_b -> out
    gemm_mma_kernel<false><<<dim3(2, 64), 256, GEMM_SMEM>>>(attnp, w2p, f2_b, out, HH);
}

// round 4
// speedup vs baseline: 2.6648x; 1.5100x over previous
#include <cuda_runtime.h>
#include <cstdint>

#define BB 8
#define NN 1024
#define HH 512

// Scratch (allocation-free rule: __device__ globals)
__device__ float g_act[(size_t)BB * NN * 4 * HH];   // 8192 x 2048 : [U | Q | K | V]
__device__ float g_attn[(size_t)BB * NN * HH];      // 8192 x 512 (gated, tf32-rounded)
__device__ float g_ts[BB * NN];                     // timestamps fp32 (seconds)
__device__ float g_xr[(size_t)BB * NN * HH];        // x rounded to tf32
__device__ float g_w1r[(size_t)4 * HH * HH];        // f1_w rounded to tf32
__device__ float g_w2r[(size_t)HH * HH];            // f2_w rounded to tf32

// ---------------------------------------------------------------------------
__device__ __forceinline__ uint32_t smem_u32(const void* p) {
    uint32_t a;
    asm("{ .reg .u64 t; cvta.to.shared.u64 t, %1; cvt.u32.u64 %0, t; }" : "=r"(a) : "l"(p));
    return a;
}
__device__ __forceinline__ float to_tf32(float x) {
    float r; asm("cvt.rna.tf32.f32 %0, %1;" : "=f"(r) : "f"(x)); return r;
}

#define CP_ASYNC16(dst, src) \
    asm volatile("cp.async.cg.shared.global [%0], [%1], 16;" :: "r"(dst), "l"(src) : "memory")
#define CP_COMMIT() asm volatile("cp.async.commit_group;" ::: "memory")
#define CP_WAIT1()  asm volatile("cp.async.wait_group 1;" ::: "memory")
#define CP_WAIT0()  asm volatile("cp.async.wait_group 0;" ::: "memory")

#define MMA_TF32(c, a, b)                                                        \
    asm volatile("mma.sync.aligned.m16n8k8.row.col.f32.tf32.tf32.f32 "           \
        "{%0,%1,%2,%3}, {%4,%5,%6,%7}, {%8,%9}, {%0,%1,%2,%3};"                  \
        : "+f"((c)[0]), "+f"((c)[1]), "+f"((c)[2]), "+f"((c)[3])                  \
        : "r"((a)[0]), "r"((a)[1]), "r"((a)[2]), "r"((a)[3]),                     \
          "r"((b)[0]), "r"((b)[1]))

// ---------------------------------------------------------------------------
// Small prep kernels
// ---------------------------------------------------------------------------
__global__ void ts_convert_kernel(const int* __restrict__ t, float* __restrict__ out) {
    bool is64 = (t[1] == 0 && t[3] == 0 && t[5] == 0 && t[7] == 0);
    int i = blockIdx.x * blockDim.x + threadIdx.x;
    if (i < BB * NN) {
        long long v = is64 ? ((const long long*)t)[i] : (long long)t[i];
        float tv = (float)v;
        out[i] = tv / 1e9f;
    }
}

__global__ void round_tf32_kernel(const float* __restrict__ in, float* __restrict__ out, int n) {
    int i = blockIdx.x * blockDim.x + threadIdx.x;
    if (i < n) out[i] = to_tf32(in[i]);
}

// ---------------------------------------------------------------------------
// mma.sync tf32 GEMM (unchanged from R3): C = A*W^T + bias (opt SiLU)
// CTA 128x256, warps 2x4, warp tile 64x64, K-chunk 32 double-buffered.
// ---------------------------------------------------------------------------
#define GK 512
#define LDS_K 36
#define A_BYTES (128 * LDS_K * 4)
#define B_BYTES (256 * LDS_K * 4)
#define STAGE_BYTES (A_BYTES + B_BYTES)
#define GEMM_SMEM (2 * STAGE_BYTES)

template<bool SILU>
__global__ __launch_bounds__(256, 1) void gemm_mma_kernel(
    const float* __restrict__ A, const float* __restrict__ W,
    const float* __restrict__ bias, float* __restrict__ C, int ldc)
{
    extern __shared__ char smem[];
    const uint32_t sb = smem_u32(smem);
    const int tid = threadIdx.x;
    const int lane = tid & 31;
    const int wid = tid >> 5;
    const int wm = wid >> 2;
    const int wn = wid & 3;
    const int l4 = lane >> 2;
    const int lc = lane & 3;
    const int m0 = blockIdx.y * 128;
    const int n0 = blockIdx.x * 256;

    auto load_stage = [&](int s, int buf) {
        uint32_t base = sb + buf * STAGE_BYTES;
        const float* a0 = A + (size_t)m0 * GK + s * 32;
        #pragma unroll
        for (int q = 0; q < 4; q++) {
            int idx = q * 256 + tid;
            int r = idx >> 3, c = idx & 7;
            CP_ASYNC16(base + r * (LDS_K * 4) + c * 16, a0 + (size_t)r * GK + c * 4);
        }
        const float* b0 = W + (size_t)n0 * GK + s * 32;
        #pragma unroll
        for (int q = 0; q < 8; q++) {
            int idx = q * 256 + tid;
            int r = idx >> 3, c = idx & 7;
            CP_ASYNC16(base + A_BYTES + r * (LDS_K * 4) + c * 16, b0 + (size_t)r * GK + c * 4);
        }
    };

    load_stage(0, 0); CP_COMMIT();
    load_stage(1, 1); CP_COMMIT();

    float acc[4][8][4];
    #pragma unroll
    for (int mt = 0; mt < 4; mt++)
        #pragma unroll
        for (int nt = 0; nt < 8; nt++)
            #pragma unroll
            for (int i = 0; i < 4; i++) acc[mt][nt][i] = 0.f;

    const int NSTAGE = GK / 32;
    #pragma unroll 1
    for (int s = 0; s < NSTAGE; s++) {
        if (s == NSTAGE - 1) { CP_WAIT0(); } else { CP_WAIT1(); }
        __syncthreads();

        const float* As = (const float*)(smem + (s & 1) * STAGE_BYTES);
        const float* Bs = (const float*)(smem + (s & 1) * STAGE_BYTES + A_BYTES);
        const int arow = wm * 64 + l4;
        const int brow = wn * 64 + l4;

        #pragma unroll
        for (int kk = 0; kk < 4; kk++) {
            int kA = kk * 8 + lc;
            uint32_t a[4][4], b[8][2];
            #pragma unroll
            for (int mt = 0; mt < 4; mt++) {
                const float* p = As + (arow + mt * 16) * LDS_K + kA;
                a[mt][0] = __float_as_uint(p[0]);
                a[mt][1] = __float_as_uint(p[8 * LDS_K]);
                a[mt][2] = __float_as_uint(p[4]);
                a[mt][3] = __float_as_uint(p[8 * LDS_K + 4]);
            }
            #pragma unroll
            for (int nt = 0; nt < 8; nt++) {
                const float* p = Bs + (brow + nt * 8) * LDS_K + kA;
                b[nt][0] = __float_as_uint(p[0]);
                b[nt][1] = __float_as_uint(p[4]);
            }
            #pragma unroll
            for (int mt = 0; mt < 4; mt++)
                #pragma unroll
                for (int nt = 0; nt < 8; nt++)
                    MMA_TF32(acc[mt][nt], a[mt], b[nt]);
        }

        __syncthreads();
        if (s + 2 < NSTAGE) { load_stage(s + 2, s & 1); CP_COMMIT(); }
    }

    #pragma unroll
    for (int mt = 0; mt < 4; mt++) {
        int r0 = m0 + wm * 64 + mt * 16 + l4;
        #pragma unroll
        for (int nt = 0; nt < 8; nt++) {
            int c0 = n0 + wn * 64 + nt * 8 + 2 * lc;
            float bv0 = bias[c0], bv1 = bias[c0 + 1];
            float v0 = acc[mt][nt][0] + bv0;
            float v1 = acc[mt][nt][1] + bv1;
            float v2 = acc[mt][nt][2] + bv0;
            float v3 = acc[mt][nt][3] + bv1;
            if (SILU) {
                v0 = __fdividef(v0, 1.f + __expf(-v0));
                v1 = __fdividef(v1, 1.f + __expf(-v1));
                v2 = __fdividef(v2, 1.f + __expf(-v2));
                v3 = __fdividef(v3, 1.f + __expf(-v3));
            }
            *(float2*)(C + (size_t)r0 * ldc + c0) = make_float2(v0, v1);
            *(float2*)(C + (size_t)(r0 + 8) * ldc + c0) = make_float2(v2, v3);
        }
    }
}

// ---------------------------------------------------------------------------
// Tensor-core attention: per (b,h,q-tile 64). k-tiles of 64 (causal).
// 4 warps: S-phase warps split keys (16 each), PV-phase warps split head-dim.
// S = tf32 mma(Q,K); epilogue bias+silu in fp32; PV = tf32 mma(S,V).
// Fused U-gating + tf32 rounding on output store.
// ---------------------------------------------------------------------------
#define PQK 68
#define PV2 72
#define PS  72

__global__ __launch_bounds__(128) void attn_tc_kernel(
    const float* __restrict__ act,
    const float* __restrict__ ts,
    const float* __restrict__ ts_w,
    const float* __restrict__ pos_w,
    float* __restrict__ attn_out)
{
    extern __shared__ float sm[];
    float* Qs  = sm;                    // 64 x 68
    float* Ks  = Qs + 64 * PQK;         // 64 x 68
    float* Vs  = Ks + 64 * PQK;         // 64 x 72 ([key][d])
    float* Ss  = Vs + 64 * PV2;         // 64 x 72
    float* tsq = Ss + 64 * PS;          // 64
    float* tsk = tsq + 64;              // 64
    float* tsw = tsk + 64;              // 65(+pad)
    float* psm = tsw + 68;              // 128

    const int tid = threadIdx.x;
    const int lane = tid & 31;
    const int w = tid >> 5;
    const int l4 = lane >> 2;
    const int lc = lane & 3;
    const int qt = blockIdx.x;
    const int bh = blockIdx.y;
    const int b = bh >> 3, h = bh & 7;
    const int q0 = qt * 64;

    const float* actb = act + (size_t)b * NN * 2048;

    // Q tile (tf32-rounded on store)
    for (int i = tid; i < 64 * 16; i += 128) {
        int r = i >> 4, c4 = (i & 15) * 4;
        float4 v = *(const float4*)(actb + (size_t)(q0 + r) * 2048 + 512 + h * 64 + c4);
        Qs[r * PQK + c4 + 0] = to_tf32(v.x);
        Qs[r * PQK + c4 + 1] = to_tf32(v.y);
        Qs[r * PQK + c4 + 2] = to_tf32(v.z);
        Qs[r * PQK + c4 + 3] = to_tf32(v.w);
    }
    if (tid < 64) {
        int qq = min(q0 + tid + 1, NN - 1);
        tsq[tid] = ts[b * NN + qq];
    }
    if (tid < 65) tsw[tid] = ts_w[tid];

    float acc[4][2][4];
    #pragma unroll
    for (int mt = 0; mt < 4; mt++)
        #pragma unroll
        for (int nt = 0; nt < 2; nt++)
            #pragma unroll
            for (int j = 0; j < 4; j++) acc[mt][nt][j] = 0.f;

    #pragma unroll 1
    for (int kt = 0; kt <= qt; kt++) {
        const int k0 = kt * 64;
        __syncthreads();   // prev PV readers of Vs/Ss done

        // K (tf32) / V (tf32) tiles
        for (int i = tid; i < 64 * 16; i += 128) {
            int r = i >> 4, c4 = (i & 15) * 4;
            float4 kv = *(const float4*)(actb + (size_t)(k0 + r) * 2048 + 1024 + h * 64 + c4);
            Ks[r * PQK + c4 + 0] = to_tf32(kv.x);
            Ks[r * PQK + c4 + 1] = to_tf32(kv.y);
            Ks[r * PQK + c4 + 2] = to_tf32(kv.z);
            Ks[r * PQK + c4 + 3] = to_tf32(kv.w);
            float4 vv = *(const float4*)(actb + (size_t)(k0 + r) * 2048 + 1536 + h * 64 + c4);
            Vs[r * PV2 + c4 + 0] = to_tf32(vv.x);
            Vs[r * PV2 + c4 + 1] = to_tf32(vv.y);
            Vs[r * PV2 + c4 + 2] = to_tf32(vv.z);
            Vs[r * PV2 + c4 + 3] = to_tf32(vv.w);
        }
        if (tid < 64) tsk[tid] = ts[b * NN + k0 + tid];
        psm[tid] = pos_w[(NN - 1) + k0 - q0 - 63 + tid];   // diff+63 in [0,126]
        __syncthreads();

        // --- S = Q K^T (warp w covers keys [w*16, w*16+16)) ---
        float sacc[4][2][4];
        #pragma unroll
        for (int mt = 0; mt < 4; mt++)
            #pragma unroll
            for (int nt = 0; nt < 2; nt++)
                #pragma unroll
                for (int j = 0; j < 4; j++) sacc[mt][nt][j] = 0.f;

        #pragma unroll
        for (int ks = 0; ks < 8; ks++) {
            int kA = ks * 8 + lc;
            uint32_t a[4][4], bb[2][2];
            #pragma unroll
            for (int mt = 0; mt < 4; mt++) {
                const float* p = Qs + (mt * 16 + l4) * PQK + kA;
                a[mt][0] = __float_as_uint(p[0]);
                a[mt][1] = __float_as_uint(p[8 * PQK]);
                a[mt][2] = __float_as_uint(p[4]);
                a[mt][3] = __float_as_uint(p[8 * PQK + 4]);
            }
            #pragma unroll
            for (int nt = 0; nt < 2; nt++) {
                const float* p = Ks + (w * 16 + nt * 8 + l4) * PQK + kA;
                bb[nt][0] = __float_as_uint(p[0]);
                bb[nt][1] = __float_as_uint(p[4]);
            }
            #pragma unroll
            for (int mt = 0; mt < 4; mt++)
                #pragma unroll
                for (int nt = 0; nt < 2; nt++)
                    MMA_TF32(sacc[mt][nt], a[mt], bb[nt]);
        }

        // --- epilogue: bias + silu + mask, store tf32 weights to Ss ---
        const bool diag = (kt == qt);
        #pragma unroll
        for (int mt = 0; mt < 4; mt++) {
            #pragma unroll
            for (int nt = 0; nt < 2; nt++) {
                int kl = w * 16 + nt * 8 + 2 * lc;
                float tk0 = tsk[kl], tk1 = tsk[kl + 1];
                #pragma unroll
                for (int half = 0; half < 2; half++) {
                    int ql = mt * 16 + l4 + half * 8;
                    float tq = tsq[ql];
                    #pragma unroll
                    for (int jj = 0; jj < 2; jj++) {
                        float raw = sacc[mt][nt][half * 2 + jj];
                        int klj = kl + jj;
                        float tk = jj ? tk1 : tk0;
                        float val = 0.f;
                        if (!diag || (klj <= ql)) {
                            float ad = fmaxf(fabsf(tq - tk), 1.0f);
                            int bucket = (int)floorf(__logf(ad) * 3.3222591f);
                            bucket = bucket < 0 ? 0 : (bucket > 64 ? 64 : bucket);
                            float sc = raw * 0.125f + psm[klj - ql + 63] + tsw[bucket];
                            val = __fdividef(sc, 1.f + __expf(-sc));
                        }
                        Ss[ql * PS + klj] = to_tf32(val);
                    }
                }
            }
        }
        __syncthreads();

        // --- PV: acc += S @ V (warp w covers d-cols [w*16, w*16+16)) ---
        #pragma unroll
        for (int ks = 0; ks < 8; ks++) {
            int kA = ks * 8 + lc;
            uint32_t a[4][4], bb[2][2];
            #pragma unroll
            for (int mt = 0; mt < 4; mt++) {
                const float* p = Ss + (mt * 16 + l4) * PS + kA;
                a[mt][0] = __float_as_uint(p[0]);
                a[mt][1] = __float_as_uint(p[8 * PS]);
                a[mt][2] = __float_as_uint(p[4]);
                a[mt][3] = __float_as_uint(p[8 * PS + 4]);
            }
            #pragma unroll
            for (int nt = 0; nt < 2; nt++) {
                const float* p = Vs + (ks * 8 + lc) * PV2 + w * 16 + nt * 8 + l4;
                bb[nt][0] = __float_as_uint(p[0]);
                bb[nt][1] = __float_as_uint(p[4 * PV2]);
            }
            #pragma unroll
            for (int mt = 0; mt < 4; mt++)
                #pragma unroll
                for (int nt = 0; nt < 2; nt++)
                    MMA_TF32(acc[mt][nt], a[mt], bb[nt]);
        }
    }

    // --- output: gate by U, round to tf32 for GEMM2 ---
    #pragma unroll
    for (int mt = 0; mt < 4; mt++) {
        #pragma unroll
        for (int half = 0; half < 2; half++) {
            int q = q0 + mt * 16 + l4 + half * 8;
            #pragma unroll
            for (int nt = 0; nt < 2; nt++) {
                int d = w * 16 + nt * 8 + 2 * lc;
                float2 uv = *(const float2*)(actb + (size_t)q * 2048 + h * 64 + d);
                float2 o;
                o.x = to_tf32(acc[mt][nt][half * 2 + 0] * uv.x);
                o.y = to_tf32(acc[mt][nt][half * 2 + 1] * uv.y);
                *(float2*)(attn_out + ((size_t)b * NN + q) * HH + h * 64 + d) = o;
            }
        }
    }
}

#define ATTN_SMEM ((64 * PQK * 2 + 64 * PV2 + 64 * PS + 64 + 64 + 68 + 128) * 4)

// ---------------------------------------------------------------------------
extern "C" void kernel_launch(void* const* d_in, const int* in_sizes, int n_in,
                              void* d_out, int out_size) {
    const float* x     = (const float*)d_in[0];
    const int*   tsi   = (const int*)  d_in[1];
    const float* f1_w  = (const float*)d_in[3];
    const float* f1_b  = (const float*)d_in[4];
    const float* f2_w  = (const float*)d_in[5];
    const float* f2_b  = (const float*)d_in[6];
    const float* ts_w  = (const float*)d_in[7];
    const float* pos_w = (const float*)d_in[8];
    float* out = (float*)d_out;

    float *actp, *attnp, *tsp, *xrp, *w1p, *w2p;
    cudaGetSymbolAddress((void**)&actp, g_act);
    cudaGetSymbolAddress((void**)&attnp, g_attn);
    cudaGetSymbolAddress((void**)&tsp, g_ts);
    cudaGetSymbolAddress((void**)&xrp, g_xr);
    cudaGetSymbolAddress((void**)&w1p, g_w1r);
    cudaGetSymbolAddress((void**)&w2p, g_w2r);

    cudaFuncSetAttribute(gemm_mma_kernel<true>,
                         cudaFuncAttributeMaxDynamicSharedMemorySize, GEMM_SMEM);
    cudaFuncSetAttribute(gemm_mma_kernel<false>,
                         cudaFuncAttributeMaxDynamicSharedMemorySize, GEMM_SMEM);
    cudaFuncSetAttribute(attn_tc_kernel,
                         cudaFuncAttributeMaxDynamicSharedMemorySize, ATTN_SMEM);

    ts_convert_kernel<<<32, 256>>>(tsi, tsp);

    // Round MMA inputs to tf32 (RNA)
    round_tf32_kernel<<<(BB * NN * HH + 255) / 256, 256>>>(x, xrp, BB * NN * HH);
    round_tf32_kernel<<<(4 * HH * HH + 255) / 256, 256>>>(f1_w, w1p, 4 * HH * HH);
    round_tf32_kernel<<<(HH * HH + 255) / 256, 256>>>(f2_w, w2p, HH * HH);

    // GEMM1 + SiLU: [8192,512] @ [2048,512]^T -> g_act [8192,2048]
    gemm_mma_kernel<true><<<dim3(8, 64), 256, GEMM_SMEM>>>(xrp, w1p, f1_b, actp, 4 * HH);

    // Tensor-core attention (+ fused U gating, tf32 round): -> g_attn
    attn_tc_kernel<<<dim3(16, 64), 128, ATTN_SMEM>>>(actp, tsp, ts_w, pos_w, attnp);

    // GEMM2: gated @ [512,512]^T + f2_b -> out
    gemm_mma_kernel<false><<<dim3(2, 64), 256, GEMM_SMEM>>>(attnp, w2p, f2_b, out, HH);
}

// round 5
// speedup vs baseline: 3.3269x; 1.2485x over previous
#include <cuda_runtime.h>
#include <cstdint>

#define BB 8
#define NN 1024
#define HH 512

// Scratch (allocation-free rule: __device__ globals)
__device__ float g_act[(size_t)BB * NN * 4 * HH];   // 8192 x 2048 : [U | Q | K | V]
__device__ float g_attn[(size_t)BB * NN * HH];      // 8192 x 512 (gated, tf32-rounded)
__device__ float g_ts[BB * NN];                     // timestamps fp32 (seconds)
__device__ float g_xr[(size_t)BB * NN * HH];        // x rounded to tf32
__device__ float g_w1r[(size_t)4 * HH * HH];        // f1_w rounded to tf32
__device__ float g_w2r[(size_t)HH * HH];            // f2_w rounded to tf32
__device__ float g_bias[(size_t)BB * NN * NN];      // rel-attn bias (head-independent)

// ---------------------------------------------------------------------------
__device__ __forceinline__ uint32_t smem_u32(const void* p) {
    uint32_t a;
    asm("{ .reg .u64 t; cvta.to.shared.u64 t, %1; cvt.u32.u64 %0, t; }" : "=r"(a) : "l"(p));
    return a;
}
__device__ __forceinline__ float to_tf32(float x) {
    float r; asm("cvt.rna.tf32.f32 %0, %1;" : "=f"(r) : "f"(x)); return r;
}

#define CP_ASYNC16(dst, src) \
    asm volatile("cp.async.cg.shared.global [%0], [%1], 16;" :: "r"(dst), "l"(src) : "memory")
#define CP_COMMIT() asm volatile("cp.async.commit_group;" ::: "memory")
#define CP_WAIT1()  asm volatile("cp.async.wait_group 1;" ::: "memory")
#define CP_WAIT0()  asm volatile("cp.async.wait_group 0;" ::: "memory")

#define MMA_TF32(c, a, b)                                                        \
    asm volatile("mma.sync.aligned.m16n8k8.row.col.f32.tf32.tf32.f32 "           \
        "{%0,%1,%2,%3}, {%4,%5,%6,%7}, {%8,%9}, {%0,%1,%2,%3};"                  \
        : "+f"((c)[0]), "+f"((c)[1]), "+f"((c)[2]), "+f"((c)[3])                  \
        : "r"((a)[0]), "r"((a)[1]), "r"((a)[2]), "r"((a)[3]),                     \
          "r"((b)[0]), "r"((b)[1]))

// ---------------------------------------------------------------------------
// Prep kernels
// ---------------------------------------------------------------------------
__global__ void ts_convert_kernel(const int* __restrict__ t, float* __restrict__ out) {
    bool is64 = (t[1] == 0 && t[3] == 0 && t[5] == 0 && t[7] == 0);
    int i = blockIdx.x * blockDim.x + threadIdx.x;
    if (i < BB * NN) {
        long long v = is64 ? ((const long long*)t)[i] : (long long)t[i];
        float tv = (float)v;
        out[i] = tv / 1e9f;
    }
}

__global__ void round_tf32_kernel(const float* __restrict__ in, float* __restrict__ out, int n) {
    int i = blockIdx.x * blockDim.x + threadIdx.x;
    if (i < n) out[i] = to_tf32(in[i]);
}

// Precompute bias[b][q][k] = pos_w[N-1+k-q] + ts_w[bucket(|ts_ext[q+1]-ts[k]|)]
// Head-independent -> computed once instead of 8x inside attention.
// Grid: (136 causal 64x64 tiles, B). Upper-triangle entries of diagonal tiles
// are computed too (finite, masked later).
__global__ __launch_bounds__(256) void bias_kernel(
    const float* __restrict__ ts, const float* __restrict__ ts_w,
    const float* __restrict__ pos_w, float* __restrict__ bias)
{
    int b = blockIdx.y;
    int idx = blockIdx.x;
    int qt = (int)((sqrtf(8.f * idx + 1.f) - 1.f) * 0.5f);
    while ((qt + 1) * (qt + 2) / 2 <= idx) qt++;
    while (qt * (qt + 1) / 2 > idx) qt--;
    int kt = idx - qt * (qt + 1) / 2;
    int q0 = qt * 64, k0 = kt * 64;
    const float* tsb = ts + b * NN;
    int tid = threadIdx.x;

    #pragma unroll
    for (int it = 0; it < 4; it++) {
        int r = (tid >> 4) + it * 16;
        int c = (tid & 15) * 4;
        int q = q0 + r;
        float tq = tsb[min(q + 1, NN - 1)];
        float4 o;
        #pragma unroll
        for (int j = 0; j < 4; j++) {
            int k = k0 + c + j;
            float ad = fmaxf(fabsf(tq - tsb[k]), 1.0f);
            int bucket = (int)floorf(__logf(ad) * 3.3222591f);
            bucket = bucket < 0 ? 0 : (bucket > 64 ? 64 : bucket);
            ((float*)&o)[j] = pos_w[NN - 1 + k - q] + ts_w[bucket];
        }
        *(float4*)(bias + ((size_t)(b * NN + q)) * NN + k0 + c) = o;
    }
}

// ---------------------------------------------------------------------------
// mma.sync tf32 GEMM (unchanged): C = A*W^T + bias (opt SiLU)
// ---------------------------------------------------------------------------
#define GK 512
#define LDS_K 36
#define A_BYTES (128 * LDS_K * 4)
#define B_BYTES (256 * LDS_K * 4)
#define STAGE_BYTES (A_BYTES + B_BYTES)
#define GEMM_SMEM (2 * STAGE_BYTES)

template<bool SILU>
__global__ __launch_bounds__(256, 1) void gemm_mma_kernel(
    const float* __restrict__ A, const float* __restrict__ W,
    const float* __restrict__ bias, float* __restrict__ C, int ldc)
{
    extern __shared__ char smem[];
    const uint32_t sb = smem_u32(smem);
    const int tid = threadIdx.x;
    const int lane = tid & 31;
    const int wid = tid >> 5;
    const int wm = wid >> 2;
    const int wn = wid & 3;
    const int l4 = lane >> 2;
    const int lc = lane & 3;
    const int m0 = blockIdx.y * 128;
    const int n0 = blockIdx.x * 256;

    auto load_stage = [&](int s, int buf) {
        uint32_t base = sb + buf * STAGE_BYTES;
        const float* a0 = A + (size_t)m0 * GK + s * 32;
        #pragma unroll
        for (int q = 0; q < 4; q++) {
            int idx = q * 256 + tid;
            int r = idx >> 3, c = idx & 7;
            CP_ASYNC16(base + r * (LDS_K * 4) + c * 16, a0 + (size_t)r * GK + c * 4);
        }
        const float* b0 = W + (size_t)n0 * GK + s * 32;
        #pragma unroll
        for (int q = 0; q < 8; q++) {
            int idx = q * 256 + tid;
            int r = idx >> 3, c = idx & 7;
            CP_ASYNC16(base + A_BYTES + r * (LDS_K * 4) + c * 16, b0 + (size_t)r * GK + c * 4);
        }
    };

    load_stage(0, 0); CP_COMMIT();
    load_stage(1, 1); CP_COMMIT();

    float acc[4][8][4];
    #pragma unroll
    for (int mt = 0; mt < 4; mt++)
        #pragma unroll
        for (int nt = 0; nt < 8; nt++)
            #pragma unroll
            for (int i = 0; i < 4; i++) acc[mt][nt][i] = 0.f;

    const int NSTAGE = GK / 32;
    #pragma unroll 1
    for (int s = 0; s < NSTAGE; s++) {
        if (s == NSTAGE - 1) { CP_WAIT0(); } else { CP_WAIT1(); }
        __syncthreads();

        const float* As = (const float*)(smem + (s & 1) * STAGE_BYTES);
        const float* Bs = (const float*)(smem + (s & 1) * STAGE_BYTES + A_BYTES);
        const int arow = wm * 64 + l4;
        const int brow = wn * 64 + l4;

        #pragma unroll
        for (int kk = 0; kk < 4; kk++) {
            int kA = kk * 8 + lc;
            uint32_t a[4][4], b[8][2];
            #pragma unroll
            for (int mt = 0; mt < 4; mt++) {
                const float* p = As + (arow + mt * 16) * LDS_K + kA;
                a[mt][0] = __float_as_uint(p[0]);
                a[mt][1] = __float_as_uint(p[8 * LDS_K]);
                a[mt][2] = __float_as_uint(p[4]);
                a[mt][3] = __float_as_uint(p[8 * LDS_K + 4]);
            }
            #pragma unroll
            for (int nt = 0; nt < 8; nt++) {
                const float* p = Bs + (brow + nt * 8) * LDS_K + kA;
                b[nt][0] = __float_as_uint(p[0]);
                b[nt][1] = __float_as_uint(p[4]);
            }
            #pragma unroll
            for (int mt = 0; mt < 4; mt++)
                #pragma unroll
                for (int nt = 0; nt < 8; nt++)
                    MMA_TF32(acc[mt][nt], a[mt], b[nt]);
        }

        __syncthreads();
        if (s + 2 < NSTAGE) { load_stage(s + 2, s & 1); CP_COMMIT(); }
    }

    #pragma unroll
    for (int mt = 0; mt < 4; mt++) {
        int r0 = m0 + wm * 64 + mt * 16 + l4;
        #pragma unroll
        for (int nt = 0; nt < 8; nt++) {
            int c0 = n0 + wn * 64 + nt * 8 + 2 * lc;
            float bv0 = bias[c0], bv1 = bias[c0 + 1];
            float v0 = acc[mt][nt][0] + bv0;
            float v1 = acc[mt][nt][1] + bv1;
            float v2 = acc[mt][nt][2] + bv0;
            float v3 = acc[mt][nt][3] + bv1;
            if (SILU) {
                v0 = __fdividef(v0, 1.f + __expf(-v0));
                v1 = __fdividef(v1, 1.f + __expf(-v1));
                v2 = __fdividef(v2, 1.f + __expf(-v2));
                v3 = __fdividef(v3, 1.f + __expf(-v3));
            }
            *(float2*)(C + (size_t)r0 * ldc + c0) = make_float2(v0, v1);
            *(float2*)(C + (size_t)(r0 + 8) * ldc + c0) = make_float2(v2, v3);
        }
    }
}

// ---------------------------------------------------------------------------
// Tensor-core attention with precomputed bias.
// Ss buffer double-duty: cp.async bias tile in -> epilogue RMW -> silu weights.
// Q prescaled by 0.125 (exact in tf32). Heavy q-tiles launched first.
// ---------------------------------------------------------------------------
#define PQK 68
#define PV2 72
#define PS  72
#define ATTN_SMEM ((64 * PQK * 2 + 64 * PV2 + 64 * PS) * 4)

__global__ __launch_bounds__(128) void attn_tc_kernel(
    const float* __restrict__ act,
    const float* __restrict__ bias,
    float* __restrict__ attn_out)
{
    extern __shared__ float sm[];
    float* Qs = sm;                     // 64 x 68
    float* Ks = Qs + 64 * PQK;          // 64 x 68
    float* Vs = Ks + 64 * PQK;          // 64 x 72 ([key][d])
    float* Ss = Vs + 64 * PV2;          // 64 x 72 (bias in / weights out)
    const uint32_t ss_base = smem_u32(Ss);

    const int tid = threadIdx.x;
    const int lane = tid & 31;
    const int w = tid >> 5;
    const int l4 = lane >> 2;
    const int lc = lane & 3;
    const int qt = 15 - blockIdx.x;     // heavy tiles first
    const int bh = blockIdx.y;
    const int b = bh >> 3, h = bh & 7;
    const int q0 = qt * 64;

    const float* actb = act + (size_t)b * NN * 2048;

    // Q tile: prescale by 0.125 (exact), round to tf32
    for (int i = tid; i < 64 * 16; i += 128) {
        int r = i >> 4, c4 = (i & 15) * 4;
        float4 v = *(const float4*)(actb + (size_t)(q0 + r) * 2048 + 512 + h * 64 + c4);
        Qs[r * PQK + c4 + 0] = to_tf32(v.x * 0.125f);
        Qs[r * PQK + c4 + 1] = to_tf32(v.y * 0.125f);
        Qs[r * PQK + c4 + 2] = to_tf32(v.z * 0.125f);
        Qs[r * PQK + c4 + 3] = to_tf32(v.w * 0.125f);
    }

    float acc[4][2][4];
    #pragma unroll
    for (int mt = 0; mt < 4; mt++)
        #pragma unroll
        for (int nt = 0; nt < 2; nt++)
            #pragma unroll
            for (int j = 0; j < 4; j++) acc[mt][nt][j] = 0.f;

    #pragma unroll 1
    for (int kt = 0; kt <= qt; kt++) {
        const int k0 = kt * 64;
        __syncthreads();   // prev-iter readers of Ss/Ks/Vs done

        // bias tile -> Ss via cp.async (overlaps with K/V LDG below)
        const float* bsrc = bias + ((size_t)(b * NN + q0)) * NN + k0;
        #pragma unroll
        for (int q8 = 0; q8 < 8; q8++) {
            int idx = q8 * 128 + tid;
            int r = idx >> 4, c = idx & 15;
            CP_ASYNC16(ss_base + (r * PS + c * 4) * 4, bsrc + (size_t)r * NN + c * 4);
        }
        CP_COMMIT();

        // K / V tiles (tf32-rounded)
        for (int i = tid; i < 64 * 16; i += 128) {
            int r = i >> 4, c4 = (i & 15) * 4;
            float4 kv = *(const float4*)(actb + (size_t)(k0 + r) * 2048 + 1024 + h * 64 + c4);
            Ks[r * PQK + c4 + 0] = to_tf32(kv.x);
            Ks[r * PQK + c4 + 1] = to_tf32(kv.y);
            Ks[r * PQK + c4 + 2] = to_tf32(kv.z);
            Ks[r * PQK + c4 + 3] = to_tf32(kv.w);
            float4 vv = *(const float4*)(actb + (size_t)(k0 + r) * 2048 + 1536 + h * 64 + c4);
            Vs[r * PV2 + c4 + 0] = to_tf32(vv.x);
            Vs[r * PV2 + c4 + 1] = to_tf32(vv.y);
            Vs[r * PV2 + c4 + 2] = to_tf32(vv.z);
            Vs[r * PV2 + c4 + 3] = to_tf32(vv.w);
        }
        CP_WAIT0();
        __syncthreads();

        // --- S = (Q*scale) K^T (warp w covers keys [w*16, w*16+16)) ---
        float sacc[4][2][4];
        #pragma unroll
        for (int mt = 0; mt < 4; mt++)
            #pragma unroll
            for (int nt = 0; nt < 2; nt++)
                #pragma unroll
                for (int j = 0; j < 4; j++) sacc[mt][nt][j] = 0.f;

        #pragma unroll
        for (int ks = 0; ks < 8; ks++) {
            int kA = ks * 8 + lc;
            uint32_t a[4][4], bb[2][2];
            #pragma unroll
            for (int mt = 0; mt < 4; mt++) {
                const float* p = Qs + (mt * 16 + l4) * PQK + kA;
                a[mt][0] = __float_as_uint(p[0]);
                a[mt][1] = __float_as_uint(p[8 * PQK]);
                a[mt][2] = __float_as_uint(p[4]);
                a[mt][3] = __float_as_uint(p[8 * PQK + 4]);
            }
            #pragma unroll
            for (int nt = 0; nt < 2; nt++) {
                const float* p = Ks + (w * 16 + nt * 8 + l4) * PQK + kA;
                bb[nt][0] = __float_as_uint(p[0]);
                bb[nt][1] = __float_as_uint(p[4]);
            }
            #pragma unroll
            for (int mt = 0; mt < 4; mt++)
                #pragma unroll
                for (int nt = 0; nt < 2; nt++)
                    MMA_TF32(sacc[mt][nt], a[mt], bb[nt]);
        }

        // --- epilogue: score + bias -> silu -> mask; RMW Ss in-place ---
        const bool diag = (kt == qt);
        #pragma unroll
        for (int mt = 0; mt < 4; mt++) {
            #pragma unroll
            for (int nt = 0; nt < 2; nt++) {
                int kl = w * 16 + nt * 8 + 2 * lc;
                #pragma unroll
                for (int half = 0; half < 2; half++) {
                    int ql = mt * 16 + l4 + half * 8;
                    float2 bv = *(const float2*)&Ss[ql * PS + kl];
                    float sc0 = sacc[mt][nt][half * 2 + 0] + bv.x;
                    float sc1 = sacc[mt][nt][half * 2 + 1] + bv.y;
                    float v0 = __fdividef(sc0, 1.f + __expf(-sc0));
                    float v1 = __fdividef(sc1, 1.f + __expf(-sc1));
                    if (diag) {
                        if (kl > ql) v0 = 0.f;
                        if (kl + 1 > ql) v1 = 0.f;
                    }
                    float2 o; o.x = to_tf32(v0); o.y = to_tf32(v1);
                    *(float2*)&Ss[ql * PS + kl] = o;
                }
            }
        }
        __syncthreads();

        // --- PV: acc += S @ V (warp w covers d-cols [w*16, w*16+16)) ---
        #pragma unroll
        for (int ks = 0; ks < 8; ks++) {
            int kA = ks * 8 + lc;
            uint32_t a[4][4], bb[2][2];
            #pragma unroll
            for (int mt = 0; mt < 4; mt++) {
                const float* p = Ss + (mt * 16 + l4) * PS + kA;
                a[mt][0] = __float_as_uint(p[0]);
                a[mt][1] = __float_as_uint(p[8 * PS]);
                a[mt][2] = __float_as_uint(p[4]);
                a[mt][3] = __float_as_uint(p[8 * PS + 4]);
            }
            #pragma unroll
            for (int nt = 0; nt < 2; nt++) {
                const float* p = Vs + (ks * 8 + lc) * PV2 + w * 16 + nt * 8 + l4;
                bb[nt][0] = __float_as_uint(p[0]);
                bb[nt][1] = __float_as_uint(p[4 * PV2]);
            }
            #pragma unroll
            for (int mt = 0; mt < 4; mt++)
                #pragma unroll
                for (int nt = 0; nt < 2; nt++)
                    MMA_TF32(acc[mt][nt], a[mt], bb[nt]);
        }
    }

    // --- output: gate by U, round to tf32 for GEMM2 ---
    #pragma unroll
    for (int mt = 0; mt < 4; mt++) {
        #pragma unroll
        for (int half = 0; half < 2; half++) {
            int q = q0 + mt * 16 + l4 + half * 8;
            #pragma unroll
            for (int nt = 0; nt < 2; nt++) {
                int d = w * 16 + nt * 8 + 2 * lc;
                float2 uv = *(const float2*)(actb + (size_t)q * 2048 + h * 64 + d);
                float2 o;
                o.x = to_tf32(acc[mt][nt][half * 2 + 0] * uv.x);
                o.y = to_tf32(acc[mt][nt][half * 2 + 1] * uv.y);
                *(float2*)(attn_out + ((size_t)b * NN + q) * HH + h * 64 + d) = o;
            }
        }
    }
}

// ---------------------------------------------------------------------------
extern "C" void kernel_launch(void* const* d_in, const int* in_sizes, int n_in,
                              void* d_out, int out_size) {
    const float* x     = (const float*)d_in[0];
    const int*   tsi   = (const int*)  d_in[1];
    const float* f1_w  = (const float*)d_in[3];
    const float* f1_b  = (const float*)d_in[4];
    const float* f2_w  = (const float*)d_in[5];
    const float* f2_b  = (const float*)d_in[6];
    const float* ts_w  = (const float*)d_in[7];
    const float* pos_w = (const float*)d_in[8];
    float* out = (float*)d_out;

    float *actp, *attnp, *tsp, *xrp, *w1p, *w2p, *biasp;
    cudaGetSymbolAddress((void**)&actp, g_act);
    cudaGetSymbolAddress((void**)&attnp, g_attn);
    cudaGetSymbolAddress((void**)&tsp, g_ts);
    cudaGetSymbolAddress((void**)&xrp, g_xr);
    cudaGetSymbolAddress((void**)&w1p, g_w1r);
    cudaGetSymbolAddress((void**)&w2p, g_w2r);
    cudaGetSymbolAddress((void**)&biasp, g_bias);

    cudaFuncSetAttribute(gemm_mma_kernel<true>,
                         cudaFuncAttributeMaxDynamicSharedMemorySize, GEMM_SMEM);
    cudaFuncSetAttribute(gemm_mma_kernel<false>,
                         cudaFuncAttributeMaxDynamicSharedMemorySize, GEMM_SMEM);
    cudaFuncSetAttribute(attn_tc_kernel,
                         cudaFuncAttributeMaxDynamicSharedMemorySize, ATTN_SMEM);

    ts_convert_kernel<<<32, 256>>>(tsi, tsp);

    // Round MMA inputs to tf32 (RNA)
    round_tf32_kernel<<<(BB * NN * HH + 255) / 256, 256>>>(x, xrp, BB * NN * HH);
    round_tf32_kernel<<<(4 * HH * HH + 255) / 256, 256>>>(f1_w, w1p, 4 * HH * HH);
    round_tf32_kernel<<<(HH * HH + 255) / 256, 256>>>(f2_w, w2p, HH * HH);

    // Precompute head-independent rel-attention bias (causal tiles)
    bias_kernel<<<dim3(136, BB), 256>>>(tsp, ts_w, pos_w, biasp);

    // GEMM1 + SiLU: [8192,512] @ [2048,512]^T -> g_act [8192,2048]
    gemm_mma_kernel<true><<<dim3(8, 64), 256, GEMM_SMEM>>>(xrp, w1p, f1_b, actp, 4 * HH);

    // Tensor-core attention (+ fused U gating, tf32 round): -> g_attn
    attn_tc_kernel<<<dim3(16, 64), 128, ATTN_SMEM>>>(actp, biasp, attnp);

    // GEMM2: gated @ [512,512]^T + f2_b -> out
    gemm_mma_kernel<false><<<dim3(2, 64), 256, GEMM_SMEM>>>(attnp, w2p, f2_b, out, HH);
}